// round 1
// baseline (speedup 1.0000x reference)
#include <cuda_runtime.h>
#include <math.h>

#define D_MODEL 1024
#define T_TOT   2052
#define L_SEQ   2048
#define NP      4
#define NHEADS  16
#define HD      64
#define WIN     128

// ---------------- scratch (device globals: allocation-free) ----------------
__device__ float g_QKV[3][T_TOT * D_MODEL];   // pre-conv Q,K,V
__device__ float g_QKVc[3][T_TOT * D_MODEL];  // post conv+silu(+norm)
__device__ float g_attn[L_SEQ * D_MODEL];     // attention output (seq rows only)

// ---------------- SGEMM: C[M,1024] = A[M,1024] @ W^T (W is [1024,1024] row-major) ----
#define BM 64
#define BN 64
#define BK 16

__device__ __forceinline__ void sgemm_body(const float* __restrict__ A0,  // rows [0,split)
                                           const float* __restrict__ A1,  // rows [split,M)
                                           int split, int M,
                                           const float* __restrict__ W,
                                           float* __restrict__ C)
{
    __shared__ float As[BK][BM];
    __shared__ float Bs[BK][BN];
    int tid = threadIdx.x;
    int tx = tid & 15, ty = tid >> 4;
    int rowBase = blockIdx.y * BM;
    int colBase = blockIdx.x * BN;
    int lr = tid >> 2;          // 0..63
    int lk = (tid & 3) << 2;    // 0,4,8,12

    float acc[4][4];
#pragma unroll
    for (int i = 0; i < 4; i++)
#pragma unroll
        for (int j = 0; j < 4; j++) acc[i][j] = 0.f;

    int ar = rowBase + lr;
    const float* Asrc = nullptr;
    if (ar < M) Asrc = (ar < split) ? (A0 + (size_t)ar * D_MODEL)
                                    : (A1 + (size_t)(ar - split) * D_MODEL);
    const float* Bsrc = W + (size_t)(colBase + lr) * D_MODEL;

    for (int kk = 0; kk < D_MODEL; kk += BK) {
        float4 av = Asrc ? *(const float4*)(Asrc + kk + lk) : make_float4(0.f, 0.f, 0.f, 0.f);
        float4 bv = *(const float4*)(Bsrc + kk + lk);
        As[lk + 0][lr] = av.x; As[lk + 1][lr] = av.y; As[lk + 2][lr] = av.z; As[lk + 3][lr] = av.w;
        Bs[lk + 0][lr] = bv.x; Bs[lk + 1][lr] = bv.y; Bs[lk + 2][lr] = bv.z; Bs[lk + 3][lr] = bv.w;
        __syncthreads();
#pragma unroll
        for (int k = 0; k < BK; k++) {
            float a[4], b[4];
#pragma unroll
            for (int i = 0; i < 4; i++) a[i] = As[k][ty * 4 + i];
#pragma unroll
            for (int j = 0; j < 4; j++) b[j] = Bs[k][tx * 4 + j];
#pragma unroll
            for (int i = 0; i < 4; i++)
#pragma unroll
                for (int j = 0; j < 4; j++) acc[i][j] += a[i] * b[j];
        }
        __syncthreads();
    }

#pragma unroll
    for (int i = 0; i < 4; i++) {
        int r = rowBase + ty * 4 + i;
        if (r < M)
            *(float4*)(C + (size_t)r * D_MODEL + colBase + tx * 4) =
                make_float4(acc[i][0], acc[i][1], acc[i][2], acc[i][3]);
    }
}

// QKV GEMMs: A = virtual xp = [persistent_memory(4 rows); x(2048 rows)]
__global__ void __launch_bounds__(256) sgemm_qkv_kernel(const float* __restrict__ pm,
                                                        const float* __restrict__ x,
                                                        const float* __restrict__ Wq,
                                                        const float* __restrict__ Wk,
                                                        const float* __restrict__ Wv)
{
    const float* W = (blockIdx.z == 0) ? Wq : (blockIdx.z == 1) ? Wk : Wv;
    float* C = g_QKV[blockIdx.z];
    sgemm_body(pm, x, NP, T_TOT, W, C);
}

// Final GEMM: d_out = g_attn @ Wo^T
__global__ void __launch_bounds__(256) sgemm_out_kernel(const float* __restrict__ Wo,
                                                        float* __restrict__ out)
{
    sgemm_body(g_attn, g_attn, 0, L_SEQ, Wo, out);
}

// ---------------- fused depthwise causal conv(k=3) + bias + SiLU + (L2 norm for Q,K) ----
__global__ void __launch_bounds__(256) conv_silu_norm_kernel(const float* __restrict__ qw,
                                                             const float* __restrict__ qb,
                                                             const float* __restrict__ kw,
                                                             const float* __restrict__ kb,
                                                             const float* __restrict__ vw,
                                                             const float* __restrict__ vb)
{
    int m = blockIdx.y;   // 0=Q,1=K,2=V
    int t = blockIdx.x;   // 0..T_TOT-1
    const float* w = (m == 0) ? qw : (m == 1) ? kw : vw;
    const float* b = (m == 0) ? qb : (m == 1) ? kb : vb;
    const float* X = g_QKV[m];
    float* Y = g_QKVc[m];
    int tid = threadIdx.x;

    float vals[4];
    float ss = 0.f;
#pragma unroll
    for (int i = 0; i < 4; i++) {
        int d = tid + i * 256;
        float x0 = (t >= 2) ? X[(size_t)(t - 2) * D_MODEL + d] : 0.f;
        float x1 = (t >= 1) ? X[(size_t)(t - 1) * D_MODEL + d] : 0.f;
        float x2 = X[(size_t)t * D_MODEL + d];
        float z = w[d * 3 + 0] * x0 + w[d * 3 + 1] * x1 + w[d * 3 + 2] * x2 + b[d];
        float y = z / (1.f + __expf(-z));   // SiLU
        vals[i] = y;
        ss += y * y;
    }

    // block reduction of sum-of-squares
    __shared__ float red[8];
#pragma unroll
    for (int o = 16; o > 0; o >>= 1) ss += __shfl_xor_sync(0xffffffffu, ss, o);
    if ((tid & 31) == 0) red[tid >> 5] = ss;
    __syncthreads();
    if (tid < 32) {
        float v = (tid < 8) ? red[tid] : 0.f;
#pragma unroll
        for (int o = 4; o > 0; o >>= 1) v += __shfl_xor_sync(0xffffffffu, v, o);
        if (tid == 0) red[0] = v;
    }
    __syncthreads();
    float total = red[0];

    float inv = 1.f;
    if (m < 2) inv = 1.f / fmaxf(sqrtf(total), 1e-12f);

#pragma unroll
    for (int i = 0; i < 4; i++) {
        int d = tid + i * 256;
        Y[(size_t)t * D_MODEL + d] = vals[i] * inv;
    }
}

// ---------------- attention: per (head, 128-query tile), K/V staged in smem ----------
#define KSLOTS 260   // 4 persistent + up to 255 window keys (+pad)

#define ATTN_PROCESS(SLOT)                                                        \
    do {                                                                          \
        int _s = (SLOT);                                                          \
        const float4* kr = (const float4*)(Ks + _s * HD);                         \
        float s0 = 0.f, s1 = 0.f, s2 = 0.f, s3 = 0.f;                             \
        _Pragma("unroll")                                                         \
        for (int i = 0; i < 16; i += 4) {                                         \
            float4 k0 = kr[i + 0], k1 = kr[i + 1], k2 = kr[i + 2], k3 = kr[i + 3];\
            s0 += qv[i+0].x*k0.x + qv[i+0].y*k0.y + qv[i+0].z*k0.z + qv[i+0].w*k0.w;\
            s1 += qv[i+1].x*k1.x + qv[i+1].y*k1.y + qv[i+1].z*k1.z + qv[i+1].w*k1.w;\
            s2 += qv[i+2].x*k2.x + qv[i+2].y*k2.y + qv[i+2].z*k2.z + qv[i+2].w*k2.w;\
            s3 += qv[i+3].x*k3.x + qv[i+3].y*k3.y + qv[i+3].z*k3.z + qv[i+3].w*k3.w;\
        }                                                                         \
        float p = __expf((s0 + s1 + s2 + s3) * 0.125f);                           \
        l += p;                                                                   \
        const float4* vr = (const float4*)(Vs + _s * HD);                         \
        _Pragma("unroll")                                                         \
        for (int i = 0; i < 16; i++) {                                            \
            float4 v4 = vr[i];                                                    \
            o[i].x += p * v4.x; o[i].y += p * v4.y;                               \
            o[i].z += p * v4.z; o[i].w += p * v4.w;                               \
        }                                                                         \
    } while (0)

__global__ void __launch_bounds__(128, 1) attn_kernel()
{
    extern __shared__ float sm[];
    float* Ks = sm;
    float* Vs = sm + KSLOTS * HD;

    const float* Qg = g_QKVc[0];
    const float* Kg = g_QKVc[1];
    const float* Vg = g_QKVc[2];

    int h = blockIdx.x;
    int tile = blockIdx.y;
    int q0 = NP + tile * 128;
    int kmin = q0 - (WIN - 1);
    if (kmin < NP) kmin = NP;
    int kmaxq = q0 + 127;                 // last query of the tile
    int total = 4 + (kmaxq - kmin + 1);   // persistent slots + window span
    int tid = threadIdx.x;
    int hoff = h * HD;

    // stage K/V tiles (float4 granularity)
    for (int idx = tid; idx < total * 16; idx += 128) {
        int slot = idx >> 4, c = idx & 15;
        int key = (slot < 4) ? slot : (kmin + slot - 4);
        ((float4*)Ks)[slot * 16 + c] = *(const float4*)(Kg + (size_t)key * D_MODEL + hoff + c * 4);
        ((float4*)Vs)[slot * 16 + c] = *(const float4*)(Vg + (size_t)key * D_MODEL + hoff + c * 4);
    }
    __syncthreads();

    int q = q0 + tid;
    float4 qv[16];
#pragma unroll
    for (int i = 0; i < 16; i++)
        qv[i] = *(const float4*)(Qg + (size_t)q * D_MODEL + hoff + i * 4);

    float4 o[16];
#pragma unroll
    for (int i = 0; i < 16; i++) o[i] = make_float4(0.f, 0.f, 0.f, 0.f);
    float l = 0.f;

    // persistent keys (always allowed for seq queries). Scores are bounded
    // (|s| <= 0.125 since Q,K rows are L2-normalized over all 1024 dims),
    // so exp without max-subtraction is safe.
#pragma unroll
    for (int s = 0; s < 4; s++) ATTN_PROCESS(s);

    // sliding window [max(NP, q-127), q]
    int ks = q - (WIN - 1);
    if (ks < NP) ks = NP;
    for (int k = ks; k <= q; k++) ATTN_PROCESS(4 + k - kmin);

    float inv = 1.f / l;
    float* outp = g_attn + (size_t)(q - NP) * D_MODEL + hoff;
#pragma unroll
    for (int i = 0; i < 16; i++)
        *(float4*)(outp + i * 4) = make_float4(o[i].x * inv, o[i].y * inv, o[i].z * inv, o[i].w * inv);
}

// ---------------- launch ----------------
extern "C" void kernel_launch(void* const* d_in, const int* in_sizes, int n_in,
                              void* d_out, int out_size)
{
    (void)in_sizes; (void)n_in; (void)out_size;
    const float* x  = (const float*)d_in[0];
    const float* pm = (const float*)d_in[1];
    const float* Wq = (const float*)d_in[2];
    const float* Wk = (const float*)d_in[3];
    const float* Wv = (const float*)d_in[4];
    const float* Wo = (const float*)d_in[5];
    const float* qw = (const float*)d_in[6];
    const float* qb = (const float*)d_in[7];
    const float* kw = (const float*)d_in[8];
    const float* kb = (const float*)d_in[9];
    const float* vw = (const float*)d_in[10];
    const float* vb = (const float*)d_in[11];
    float* out = (float*)d_out;

    const int attn_smem = 2 * KSLOTS * HD * (int)sizeof(float);  // 133,120 B
    cudaFuncSetAttribute(attn_kernel, cudaFuncAttributeMaxDynamicSharedMemorySize, attn_smem);

    dim3 gQKV(D_MODEL / BN, (T_TOT + BM - 1) / BM, 3);
    sgemm_qkv_kernel<<<gQKV, 256>>>(pm, x, Wq, Wk, Wv);

    conv_silu_norm_kernel<<<dim3(T_TOT, 3), 256>>>(qw, qb, kw, kb, vw, vb);

    attn_kernel<<<dim3(NHEADS, L_SEQ / 128), 128, attn_smem>>>();

    sgemm_out_kernel<<<dim3(D_MODEL / BN, L_SEQ / BM), 256>>>(Wo, out);
}

// round 3
// speedup vs baseline: 1.6228x; 1.6228x over previous
#include <cuda_runtime.h>
#include <cuda_fp16.h>
#include <math.h>
#include <stdint.h>

#define D_MODEL 1024
#define T_TOT   2052
#define MPAD    2176   // 17*128
#define L_SEQ   2048
#define NP      4
#define NHEADS  16
#define HD      64
#define WIN     128

// ---------------- scratch (device globals: allocation-free) ----------------
__device__ float g_QKV[3][T_TOT * D_MODEL];   // pre-conv Q,K,V (fp32)
__device__ float g_QKVc[3][T_TOT * D_MODEL];  // post conv+silu(+norm)
__device__ __half g_xp_h[MPAD * D_MODEL];
__device__ __half g_xp_l[MPAD * D_MODEL];
__device__ __half g_w_h[4][D_MODEL * D_MODEL];
__device__ __half g_w_l[4][D_MODEL * D_MODEL];
__device__ __half g_at_h[L_SEQ * D_MODEL];
__device__ __half g_at_l[L_SEQ * D_MODEL];

// ---------------- helpers ----------------
__device__ __forceinline__ uint32_t smem_u32(const void* p) {
    uint32_t a;
    asm("{ .reg .u64 t; cvta.to.shared.u64 t, %1; cvt.u32.u64 %0, t; }" : "=r"(a) : "l"(p));
    return a;
}

#define LDSM4(R0, R1, R2, R3, ADDR) \
    asm volatile("ldmatrix.sync.aligned.m8n8.x4.shared.b16 {%0,%1,%2,%3}, [%4];" \
                 : "=r"(R0), "=r"(R1), "=r"(R2), "=r"(R3) : "r"(ADDR))

#define MMA16816(D, A0, A1, A2, A3, B0, B1) \
    asm volatile("mma.sync.aligned.m16n8k16.row.col.f32.f16.f16.f32 " \
                 "{%0,%1,%2,%3}, {%4,%5,%6,%7}, {%8,%9}, {%0,%1,%2,%3};" \
                 : "+f"((D)[0]), "+f"((D)[1]), "+f"((D)[2]), "+f"((D)[3]) \
                 : "r"(A0), "r"(A1), "r"(A2), "r"(A3), "r"(B0), "r"(B1))

#define CP_ASYNC16(S, G) \
    asm volatile("cp.async.cg.shared.global [%0], [%1], 16;" :: "r"(S), "l"(G))
#define CP_COMMIT()  asm volatile("cp.async.commit_group;" ::: "memory")
#define CP_WAIT1()   asm volatile("cp.async.wait_group 1;" ::: "memory")

// fp16 hi/lo split of a float4 -> packed half2 words
__device__ __forceinline__ void split4h(float4 v, uint2& hi, uint2& lo) {
    __half h0 = __float2half(v.x), h1 = __float2half(v.y);
    __half h2 = __float2half(v.z), h3 = __float2half(v.w);
    __half l0 = __float2half(v.x - __half2float(h0));
    __half l1 = __float2half(v.y - __half2float(h1));
    __half l2 = __float2half(v.z - __half2float(h2));
    __half l3 = __float2half(v.w - __half2float(h3));
    hi.x = (uint32_t)__half_as_ushort(h0) | ((uint32_t)__half_as_ushort(h1) << 16);
    hi.y = (uint32_t)__half_as_ushort(h2) | ((uint32_t)__half_as_ushort(h3) << 16);
    lo.x = (uint32_t)__half_as_ushort(l0) | ((uint32_t)__half_as_ushort(l1) << 16);
    lo.y = (uint32_t)__half_as_ushort(l2) | ((uint32_t)__half_as_ushort(l3) << 16);
}

// weights -> hi/lo
__global__ void __launch_bounds__(256) convert_w_kernel(const float* __restrict__ Wq,
                                                        const float* __restrict__ Wk,
                                                        const float* __restrict__ Wv,
                                                        const float* __restrict__ Wo)
{
    int w = blockIdx.y;
    const float* src = (w == 0) ? Wq : (w == 1) ? Wk : (w == 2) ? Wv : Wo;
    int i = (blockIdx.x * 256 + threadIdx.x) * 4;
    float4 v = *(const float4*)(src + i);
    uint2 hi, lo; split4h(v, hi, lo);
    *(uint2*)(&g_w_h[w][i]) = hi;
    *(uint2*)(&g_w_l[w][i]) = lo;
}

// xp = [pm(4); x(2048); pad zeros to 2176] -> hi/lo
__global__ void __launch_bounds__(256) convert_xp_kernel(const float* __restrict__ pm,
                                                         const float* __restrict__ x)
{
    int i = (blockIdx.x * 256 + threadIdx.x) * 4;
    int row = i >> 10, col = i & 1023;
    float4 v = make_float4(0.f, 0.f, 0.f, 0.f);
    if (row < NP)          v = *(const float4*)(pm + row * D_MODEL + col);
    else if (row < T_TOT)  v = *(const float4*)(x + (size_t)(row - NP) * D_MODEL + col);
    uint2 hi, lo; split4h(v, hi, lo);
    *(uint2*)(&g_xp_h[i]) = hi;
    *(uint2*)(&g_xp_l[i]) = lo;
}

// ---------------- mma.sync GEMM: C[128,128]-tile = A @ B^T ----------------
// A,B given as fp16 hi/lo pairs; 3 mma passes (hh, hl, lh) into fp32 acc.
// SMEM per stage: Ah(16K) Al(16K) Bh(16K) Bl(16K) = 64KB, 2 stages = 128KB.
// Tiles: 128 rows x 64 halfs (128B rows), XOR-swizzled 16B chunks.
#define GEMM_SMEM (2 * 65536)

__device__ __forceinline__ void gemm128_body(const __half* __restrict__ Ah,
                                             const __half* __restrict__ Al,
                                             const __half* __restrict__ Bh,
                                             const __half* __restrict__ Bl,
                                             float* __restrict__ C, int Mrows)
{
    extern __shared__ __align__(1024) char sm[];
    uint32_t sbase = smem_u32(sm);
    int tid = threadIdx.x;
    int lane = tid & 31, wid = tid >> 5;
    int bm = blockIdx.y, bn = blockIdx.x;

    const __half* srcs[4] = {
        Ah + (size_t)bm * 128 * D_MODEL, Al + (size_t)bm * 128 * D_MODEL,
        Bh + (size_t)bn * 128 * D_MODEL, Bl + (size_t)bn * 128 * D_MODEL };

    // cp.async geometry: 4 mats * 1024 chunks of 16B; 4096 chunks / 256 thr = 16 per thread
    // chunk g: mat = g>>10, row = (g&1023)>>3, c = (g&1023)&7
    // issue one K-chunk (64 halfs = 128B per row) into stage s
    auto issue_chunk = [&](int kc, int s) {
        uint32_t stage = sbase + s * 65536;
#pragma unroll
        for (int it = 0; it < 16; it++) {
            int g = it * 256 + tid;
            int mat = g >> 10;
            int r = (g & 1023) >> 3;
            int c = g & 7;
            const __half* gp = srcs[mat] + (size_t)r * D_MODEL + kc * 64 + c * 8;
            uint32_t so = stage + mat * 16384 + r * 128 + ((c * 16) ^ ((r & 7) << 4));
            CP_ASYNC16(so, gp);
        }
    };

    // warp tiling: 4x2 warps, warp tile 32(M) x 64(N)
    int m_base = (wid & 3) * 32;
    int n_base = (wid >> 2) * 64;

    // ldmatrix lane geometry
    int arow0 = m_base + (lane & 15);            // + mi*16
    int ak2 = ((lane >> 4) * 8) * 2;             // k byte offset within frag
    int brow0 = n_base + (lane & 7) + ((lane >> 4) << 3);  // + p*16
    int bk2 = (((lane >> 3) & 1) * 8) * 2;

    uint32_t aoffs[2], asw[2], boffs[4], bsw[4];
#pragma unroll
    for (int mi = 0; mi < 2; mi++) {
        int r = arow0 + mi * 16;
        aoffs[mi] = r * 128; asw[mi] = (r & 7) << 4;
    }
#pragma unroll
    for (int p = 0; p < 4; p++) {
        int r = brow0 + p * 16;
        boffs[p] = r * 128; bsw[p] = (r & 7) << 4;
    }

    float acc[2][8][4];
#pragma unroll
    for (int mi = 0; mi < 2; mi++)
#pragma unroll
        for (int n = 0; n < 8; n++)
#pragma unroll
            for (int j = 0; j < 4; j++) acc[mi][n][j] = 0.f;

    issue_chunk(0, 0); CP_COMMIT();
    issue_chunk(1, 1); CP_COMMIT();

    for (int kc = 0; kc < 16; kc++) {
        CP_WAIT1();
        __syncthreads();
        uint32_t stage = sbase + (kc & 1) * 65536;
        uint32_t AH = stage, AL = stage + 16384, BH = stage + 32768, BL = stage + 49152;
#pragma unroll
        for (int ks = 0; ks < 4; ks++) {
            uint32_t kb2 = ks * 32;  // 16 halfs = 32B per kstep
            uint32_t ah[2][4], al[2][4];
#pragma unroll
            for (int mi = 0; mi < 2; mi++) {
                LDSM4(ah[mi][0], ah[mi][1], ah[mi][2], ah[mi][3],
                      AH + aoffs[mi] + ((kb2 + ak2) ^ asw[mi]));
                LDSM4(al[mi][0], al[mi][1], al[mi][2], al[mi][3],
                      AL + aoffs[mi] + ((kb2 + ak2) ^ asw[mi]));
            }
#pragma unroll
            for (int p = 0; p < 4; p++) {
                uint32_t bh[4], bl[4];
                LDSM4(bh[0], bh[1], bh[2], bh[3], BH + boffs[p] + ((kb2 + bk2) ^ bsw[p]));
                LDSM4(bl[0], bl[1], bl[2], bl[3], BL + boffs[p] + ((kb2 + bk2) ^ bsw[p]));
#pragma unroll
                for (int mi = 0; mi < 2; mi++) {
                    MMA16816(acc[mi][2 * p],     ah[mi][0], ah[mi][1], ah[mi][2], ah[mi][3], bh[0], bh[1]);
                    MMA16816(acc[mi][2 * p],     ah[mi][0], ah[mi][1], ah[mi][2], ah[mi][3], bl[0], bl[1]);
                    MMA16816(acc[mi][2 * p],     al[mi][0], al[mi][1], al[mi][2], al[mi][3], bh[0], bh[1]);
                    MMA16816(acc[mi][2 * p + 1], ah[mi][0], ah[mi][1], ah[mi][2], ah[mi][3], bh[2], bh[3]);
                    MMA16816(acc[mi][2 * p + 1], ah[mi][0], ah[mi][1], ah[mi][2], ah[mi][3], bl[2], bl[3]);
                    MMA16816(acc[mi][2 * p + 1], al[mi][0], al[mi][1], al[mi][2], al[mi][3], bh[2], bh[3]);
                }
            }
        }
        __syncthreads();
        int c2 = kc + 2;
        if (c2 < 16) issue_chunk(c2, kc & 1);
        CP_COMMIT();
    }

    // epilogue
    int crow = lane >> 2;
    int ccol = (lane & 3) * 2;
#pragma unroll
    for (int mi = 0; mi < 2; mi++) {
#pragma unroll
        for (int n = 0; n < 8; n++) {
            int row0 = bm * 128 + m_base + mi * 16 + crow;
            int col = bn * 128 + n_base + n * 8 + ccol;
            if (row0 < Mrows)
                *(float2*)(C + (size_t)row0 * D_MODEL + col) = make_float2(acc[mi][n][0], acc[mi][n][1]);
            int row1 = row0 + 8;
            if (row1 < Mrows)
                *(float2*)(C + (size_t)row1 * D_MODEL + col) = make_float2(acc[mi][n][2], acc[mi][n][3]);
        }
    }
}

__global__ void __launch_bounds__(256, 1) gemm_qkv_tc(void)
{
    int z = blockIdx.z;
    gemm128_body(g_xp_h, g_xp_l, g_w_h[z], g_w_l[z], g_QKV[z], T_TOT);
}
__global__ void __launch_bounds__(256, 1) gemm_out_tc(float* __restrict__ out)
{
    gemm128_body(g_at_h, g_at_l, g_w_h[3], g_w_l[3], out, L_SEQ);
}

// ---------------- fused depthwise causal conv(k=3) + bias + SiLU + (L2 norm for Q,K) ----
__global__ void __launch_bounds__(256) conv_silu_norm_kernel(const float* __restrict__ qw,
                                                             const float* __restrict__ qb,
                                                             const float* __restrict__ kw,
                                                             const float* __restrict__ kb,
                                                             const float* __restrict__ vw,
                                                             const float* __restrict__ vb)
{
    int m = blockIdx.y;
    int t = blockIdx.x;
    const float* w = (m == 0) ? qw : (m == 1) ? kw : vw;
    const float* b = (m == 0) ? qb : (m == 1) ? kb : vb;
    const float* X = g_QKV[m];
    float* Y = g_QKVc[m];
    int tid = threadIdx.x;

    float vals[4];
    float ss = 0.f;
#pragma unroll
    for (int i = 0; i < 4; i++) {
        int d = tid + i * 256;
        float x0 = (t >= 2) ? X[(size_t)(t - 2) * D_MODEL + d] : 0.f;
        float x1 = (t >= 1) ? X[(size_t)(t - 1) * D_MODEL + d] : 0.f;
        float x2 = X[(size_t)t * D_MODEL + d];
        float z = w[d * 3 + 0] * x0 + w[d * 3 + 1] * x1 + w[d * 3 + 2] * x2 + b[d];
        float y = z / (1.f + __expf(-z));
        vals[i] = y;
        ss += y * y;
    }
    __shared__ float red[8];
#pragma unroll
    for (int o = 16; o > 0; o >>= 1) ss += __shfl_xor_sync(0xffffffffu, ss, o);
    if ((tid & 31) == 0) red[tid >> 5] = ss;
    __syncthreads();
    if (tid < 32) {
        float v = (tid < 8) ? red[tid] : 0.f;
#pragma unroll
        for (int o = 4; o > 0; o >>= 1) v += __shfl_xor_sync(0xffffffffu, v, o);
        if (tid == 0) red[0] = v;
    }
    __syncthreads();
    float total = red[0];
    float inv = 1.f;
    if (m < 2) inv = 1.f / fmaxf(sqrtf(total), 1e-12f);
#pragma unroll
    for (int i = 0; i < 4; i++) {
        int d = tid + i * 256;
        Y[(size_t)t * D_MODEL + d] = vals[i] * inv;
    }
}

// ---------------- attention ----------------
#define KSLOTS 260

#define ATTN_PROCESS(SLOT)                                                        \
    do {                                                                          \
        int _s = (SLOT);                                                          \
        const float4* kr = (const float4*)(Ks + _s * HD);                         \
        float s0 = 0.f, s1 = 0.f, s2 = 0.f, s3 = 0.f;                             \
        _Pragma("unroll")                                                         \
        for (int i = 0; i < 16; i += 4) {                                         \
            float4 k0 = kr[i + 0], k1 = kr[i + 1], k2 = kr[i + 2], k3 = kr[i + 3];\
            s0 += qv[i+0].x*k0.x + qv[i+0].y*k0.y + qv[i+0].z*k0.z + qv[i+0].w*k0.w;\
            s1 += qv[i+1].x*k1.x + qv[i+1].y*k1.y + qv[i+1].z*k1.z + qv[i+1].w*k1.w;\
            s2 += qv[i+2].x*k2.x + qv[i+2].y*k2.y + qv[i+2].z*k2.z + qv[i+2].w*k2.w;\
            s3 += qv[i+3].x*k3.x + qv[i+3].y*k3.y + qv[i+3].z*k3.z + qv[i+3].w*k3.w;\
        }                                                                         \
        float p = __expf((s0 + s1 + s2 + s3) * 0.125f);                           \
        l += p;                                                                   \
        const float4* vr = (const float4*)(Vs + _s * HD);                         \
        _Pragma("unroll")                                                         \
        for (int i = 0; i < 16; i++) {                                            \
            float4 v4 = vr[i];                                                    \
            o[i].x += p * v4.x; o[i].y += p * v4.y;                               \
            o[i].z += p * v4.z; o[i].w += p * v4.w;                               \
        }                                                                         \
    } while (0)

__global__ void __launch_bounds__(128, 1) attn_kernel()
{
    extern __shared__ __align__(1024) char smc[];
    float* Ks = (float*)smc;
    float* Vs = (float*)smc + KSLOTS * HD;

    const float* Qg = g_QKVc[0];
    const float* Kg = g_QKVc[1];
    const float* Vg = g_QKVc[2];

    int h = blockIdx.x;
    int tile = blockIdx.y;
    int q0 = NP + tile * 128;
    int kmin = q0 - (WIN - 1);
    if (kmin < NP) kmin = NP;
    int kmaxq = q0 + 127;
    int total = 4 + (kmaxq - kmin + 1);
    int tid = threadIdx.x;
    int hoff = h * HD;

    for (int idx = tid; idx < total * 16; idx += 128) {
        int slot = idx >> 4, c = idx & 15;
        int key = (slot < 4) ? slot : (kmin + slot - 4);
        ((float4*)Ks)[slot * 16 + c] = *(const float4*)(Kg + (size_t)key * D_MODEL + hoff + c * 4);
        ((float4*)Vs)[slot * 16 + c] = *(const float4*)(Vg + (size_t)key * D_MODEL + hoff + c * 4);
    }
    __syncthreads();

    int q = q0 + tid;
    float4 qv[16];
#pragma unroll
    for (int i = 0; i < 16; i++)
        qv[i] = *(const float4*)(Qg + (size_t)q * D_MODEL + hoff + i * 4);

    float4 o[16];
#pragma unroll
    for (int i = 0; i < 16; i++) o[i] = make_float4(0.f, 0.f, 0.f, 0.f);
    float l = 0.f;

#pragma unroll
    for (int s = 0; s < 4; s++) ATTN_PROCESS(s);

    int ks = q - (WIN - 1);
    if (ks < NP) ks = NP;
    for (int k = ks; k <= q; k++) ATTN_PROCESS(4 + k - kmin);

    // write fp16 hi/lo split directly (consumed by the out-projection GEMM)
    float inv = 1.f / l;
    size_t rbase = (size_t)(q - NP) * D_MODEL + hoff;
#pragma unroll
    for (int i = 0; i < 16; i++) {
        float4 v = make_float4(o[i].x * inv, o[i].y * inv, o[i].z * inv, o[i].w * inv);
        uint2 hi, lo; split4h(v, hi, lo);
        *(uint2*)(&g_at_h[rbase + i * 4]) = hi;
        *(uint2*)(&g_at_l[rbase + i * 4]) = lo;
    }
}

// ---------------- launch ----------------
extern "C" void kernel_launch(void* const* d_in, const int* in_sizes, int n_in,
                              void* d_out, int out_size)
{
    (void)in_sizes; (void)n_in; (void)out_size;
    const float* x  = (const float*)d_in[0];
    const float* pm = (const float*)d_in[1];
    const float* Wq = (const float*)d_in[2];
    const float* Wk = (const float*)d_in[3];
    const float* Wv = (const float*)d_in[4];
    const float* Wo = (const float*)d_in[5];
    const float* qw = (const float*)d_in[6];
    const float* qb = (const float*)d_in[7];
    const float* kw = (const float*)d_in[8];
    const float* kb = (const float*)d_in[9];
    const float* vw = (const float*)d_in[10];
    const float* vb = (const float*)d_in[11];
    float* out = (float*)d_out;

    const int attn_smem = 2 * KSLOTS * HD * (int)sizeof(float);
    cudaFuncSetAttribute(attn_kernel, cudaFuncAttributeMaxDynamicSharedMemorySize, attn_smem);
    cudaFuncSetAttribute(gemm_qkv_tc, cudaFuncAttributeMaxDynamicSharedMemorySize, GEMM_SMEM);
    cudaFuncSetAttribute(gemm_out_tc, cudaFuncAttributeMaxDynamicSharedMemorySize, GEMM_SMEM);

    convert_w_kernel<<<dim3(D_MODEL * D_MODEL / 1024, 4), 256>>>(Wq, Wk, Wv, Wo);
    convert_xp_kernel<<<MPAD * D_MODEL / 1024, 256>>>(pm, x);

    gemm_qkv_tc<<<dim3(8, 17, 3), 256, GEMM_SMEM>>>();

    conv_silu_norm_kernel<<<dim3(T_TOT, 3), 256>>>(qw, qb, kw, kb, vw, vb);

    attn_kernel<<<dim3(NHEADS, L_SEQ / 128), 128, attn_smem>>>();

    gemm_out_tc<<<dim3(8, 16, 1), 256, GEMM_SMEM>>>(out);
}